// round 2
// baseline (speedup 1.0000x reference)
#include <cuda_runtime.h>
#include <cuda_bf16.h>
#include <cstdint>

// Problem constants (fixed by reference):
//   x         [256, 512]    f32
//   weight    [500001, 512] f32
//   bias      [500001]      f32
//   sample_ids[32768]       int32 (JAX downgrades int64 without x64 flag)
//   out       [256, 32768]  f32 : out[n][s] = dot(x[n], weight[ids[s]]) + bias[ids[s]]

namespace {
constexpr int N_ROWS = 256;     // x rows
constexpr int D      = 512;     // K
constexpr int S      = 32768;   // samples
constexpr int ROWS_W = 500001;  // weight rows
constexpr int BM     = 128;     // tile M
constexpr int BS     = 128;     // tile S
constexpr int BK     = 16;      // tile K
constexpr int TM     = 8;       // per-thread microtile
constexpr int TS     = 8;
}

__global__ __launch_bounds__(256, 2)
void lsh_sampled_gemm(const float* __restrict__ x,
                      const float* __restrict__ weight,
                      const float* __restrict__ bias,
                      const int* __restrict__ sample_ids,
                      float* __restrict__ out)
{
    __shared__ float xs[BK][BM];
    __shared__ float ws[BK][BS];
    __shared__ int   sids[BS];
    __shared__ float sbias[BS];

    const int tid = threadIdx.x;              // 0..255
    const int s0  = blockIdx.x * BS;
    const int m0  = blockIdx.y * BM;

    // Gather ids and bias for this block's 128 samples.
    if (tid < BS) {
        int id = sample_ids[s0 + tid];
        // seatbelt: clamp into table (turns a dtype surprise into a
        // correctness signal instead of an illegal access)
        id = min(max(id, 0), ROWS_W - 1);
        sids[tid]  = id;
        sbias[tid] = bias[id];
    }

    // Microtile coordinates: 16x16 thread grid, each thread owns 8x8.
    const int tm = tid >> 4;     // 0..15 -> m offset tm*8
    const int ts = tid & 15;     // 0..15 -> s offset ts*8

    // Loader coordinates: each thread loads float4s; 64 rows x 16 K per pass.
    const int lrow = tid >> 2;          // 0..63
    const int lk4  = (tid & 3) * 4;     // 0,4,8,12

    float acc[TM][TS];
    #pragma unroll
    for (int i = 0; i < TM; i++)
        #pragma unroll
        for (int j = 0; j < TS; j++)
            acc[i][j] = 0.f;

    __syncthreads();   // sids/sbias visible

    for (int k0 = 0; k0 < D; k0 += BK) {
        // ---- stage x tile (transposed: xs[k][m]) ----
        #pragma unroll
        for (int r = 0; r < 2; r++) {
            int row = lrow + r * 64;
            float4 v = *reinterpret_cast<const float4*>(&x[(size_t)(m0 + row) * D + k0 + lk4]);
            xs[lk4 + 0][row] = v.x;
            xs[lk4 + 1][row] = v.y;
            xs[lk4 + 2][row] = v.z;
            xs[lk4 + 3][row] = v.w;
        }
        // ---- stage gathered weight tile (transposed: ws[k][s]) ----
        #pragma unroll
        for (int r = 0; r < 2; r++) {
            int row = lrow + r * 64;
            const float* wr = weight + (size_t)sids[row] * D;
            float4 v = *reinterpret_cast<const float4*>(&wr[k0 + lk4]);
            ws[lk4 + 0][row] = v.x;
            ws[lk4 + 1][row] = v.y;
            ws[lk4 + 2][row] = v.z;
            ws[lk4 + 3][row] = v.w;
        }
        __syncthreads();

        // ---- compute ----
        #pragma unroll
        for (int kk = 0; kk < BK; kk++) {
            float a[TM], b[TS];
            *reinterpret_cast<float4*>(&a[0]) = *reinterpret_cast<const float4*>(&xs[kk][tm * TM + 0]);
            *reinterpret_cast<float4*>(&a[4]) = *reinterpret_cast<const float4*>(&xs[kk][tm * TM + 4]);
            *reinterpret_cast<float4*>(&b[0]) = *reinterpret_cast<const float4*>(&ws[kk][ts * TS + 0]);
            *reinterpret_cast<float4*>(&b[4]) = *reinterpret_cast<const float4*>(&ws[kk][ts * TS + 4]);
            #pragma unroll
            for (int i = 0; i < TM; i++)
                #pragma unroll
                for (int j = 0; j < TS; j++)
                    acc[i][j] = fmaf(a[i], b[j], acc[i][j]);
        }
        __syncthreads();
    }

    // ---- epilogue: add gathered bias, vectorized stores ----
    float bj[TS];
    #pragma unroll
    for (int j = 0; j < TS; j++) bj[j] = sbias[ts * TS + j];

    #pragma unroll
    for (int i = 0; i < TM; i++) {
        int m = m0 + tm * TM + i;
        float4 v0, v1;
        v0.x = acc[i][0] + bj[0]; v0.y = acc[i][1] + bj[1];
        v0.z = acc[i][2] + bj[2]; v0.w = acc[i][3] + bj[3];
        v1.x = acc[i][4] + bj[4]; v1.y = acc[i][5] + bj[5];
        v1.z = acc[i][6] + bj[6]; v1.w = acc[i][7] + bj[7];
        float* o = &out[(size_t)m * S + s0 + ts * TS];
        *reinterpret_cast<float4*>(o + 0) = v0;
        *reinterpret_cast<float4*>(o + 4) = v1;
    }
}

extern "C" void kernel_launch(void* const* d_in, const int* in_sizes, int n_in,
                              void* d_out, int out_size)
{
    const float* x    = (const float*)d_in[0];
    const float* w    = (const float*)d_in[1];
    const float* bias = (const float*)d_in[2];
    const int*   ids  = (const int*)d_in[3];
    float*       out  = (float*)d_out;

    dim3 grid(S / BS, N_ROWS / BM);   // (256, 2)
    dim3 block(256);
    lsh_sampled_gemm<<<grid, block>>>(x, w, bias, ids, out);
}

// round 4
// speedup vs baseline: 1.8831x; 1.8831x over previous
#include <cuda_runtime.h>
#include <cuda_bf16.h>
#include <cstdint>

// out[n][s] = dot(x[n,:], weight[ids[s],:]) + bias[ids[s]]
//   x [256,512] f32, weight [500001,512] f32, bias [500001] f32, ids [32768] i32
//   out [256, 32768] f32
// bf16x3 split GEMM on mma.sync (legacy tensor path; tcgen05 PTX is rejected
// because the harness emits .target sm_103 without the 'a' feature suffix).

namespace {
constexpr int D_K    = 512;
constexpr int NX     = 256;
constexpr int S_ALL  = 32768;
constexpr int ROWS_W = 500001;
constexpr int STILE  = 128;        // samples per CTA (GEMM M)
constexpr int NTILE  = 128;        // x rows per CTA (GEMM N)
constexpr int KC     = 64;         // f32 K elems per chunk
constexpr int NCH    = D_K / KC;   // 8

// smem stage layout (bytes): Ah, Al, Bh, Bl each 128 rows x 64 bf16 (128B rows)
constexpr uint32_t AH = 0, AL = 16384, BH = 32768, BL = 49152;
constexpr uint32_t STAGE = 65536;
constexpr uint32_t SMEM_BYTES = 2 * STAGE;   // 128KB (epilogue reuses this)
constexpr int CSTRIDE = 130;       // f32 stride of epilogue staging
}

__device__ __nv_bfloat16 g_xh[NX * D_K];
__device__ __nv_bfloat16 g_xl[NX * D_K];

__device__ __forceinline__ uint32_t smem_u32(const void* p) {
    uint32_t a;
    asm("{ .reg .u64 t; cvta.to.shared.u64 t, %1; cvt.u32.u64 %0, t; }" : "=r"(a) : "l"(p));
    return a;
}
__device__ __forceinline__ uint32_t sw128(uint32_t o) { return o ^ ((o >> 3) & 0x70u); }

__device__ __forceinline__ uint32_t pk(__nv_bfloat16 a, __nv_bfloat16 b) {
    __nv_bfloat162 t = __halves2bfloat162(a, b);
    return *reinterpret_cast<uint32_t*>(&t);
}
__device__ __forceinline__ uint32_t pkf(float a, float b) {
    __nv_bfloat162 t = __floats2bfloat162_rn(a, b);
    return *reinterpret_cast<uint32_t*>(&t);
}

__device__ __forceinline__ void ldsm4(uint32_t addr, uint32_t& r0, uint32_t& r1,
                                      uint32_t& r2, uint32_t& r3) {
    asm volatile("ldmatrix.sync.aligned.m8n8.x4.shared.b16 {%0,%1,%2,%3}, [%4];"
                 : "=r"(r0), "=r"(r1), "=r"(r2), "=r"(r3) : "r"(addr));
}
__device__ __forceinline__ void mma16816(float* d, const uint32_t* a, const uint32_t* b) {
    asm volatile(
        "mma.sync.aligned.m16n8k16.row.col.f32.bf16.bf16.f32 "
        "{%0,%1,%2,%3}, {%4,%5,%6,%7}, {%8,%9}, {%0,%1,%2,%3};"
        : "+f"(d[0]), "+f"(d[1]), "+f"(d[2]), "+f"(d[3])
        : "r"(a[0]), "r"(a[1]), "r"(a[2]), "r"(a[3]), "r"(b[0]), "r"(b[1]));
}
__device__ __forceinline__ void cp16(uint32_t dst, const void* src) {
    asm volatile("cp.async.ca.shared.global [%0], [%1], 16;" :: "r"(dst), "l"(src));
}

// ---------- kernel 1: split x into bf16 hi/lo ----------
__global__ void split_x_kernel(const float* __restrict__ x) {
    int i = blockIdx.x * blockDim.x + threadIdx.x;   // over 32768 float4s
    float4 v = reinterpret_cast<const float4*>(x)[i];
    __nv_bfloat16 h0 = __float2bfloat16_rn(v.x), h1 = __float2bfloat16_rn(v.y);
    __nv_bfloat16 h2 = __float2bfloat16_rn(v.z), h3 = __float2bfloat16_rn(v.w);
    float l0 = v.x - __bfloat162float(h0), l1 = v.y - __bfloat162float(h1);
    float l2 = v.z - __bfloat162float(h2), l3 = v.w - __bfloat162float(h3);
    uint2 hv, lv;
    hv.x = pk(h0, h1);  hv.y = pk(h2, h3);
    lv.x = pkf(l0, l1); lv.y = pkf(l2, l3);
    reinterpret_cast<uint2*>(g_xh)[i] = hv;
    reinterpret_cast<uint2*>(g_xl)[i] = lv;
}

// ---------- kernel 2: GEMM ----------
__global__ void __launch_bounds__(256, 1)
lsh_mma_gemm(const float* __restrict__ weight,
             const float* __restrict__ bias,
             const int* __restrict__ sample_ids,
             float* __restrict__ out)
{
    extern __shared__ float4 smem4[];
    char* smc = reinterpret_cast<char*>(smem4);
    const uint32_t sb = smem_u32(smc);

    __shared__ int   sids[STILE];
    __shared__ float sbias[STILE];

    const int tid = threadIdx.x;
    const int wid = tid >> 5;
    const int lid = tid & 31;
    const int n0  = blockIdx.x * NTILE;    // x-row half (0 or 128)
    const int s0  = blockIdx.y * STILE;    // sample tile

    if (tid < STILE) {
        int id = sample_ids[s0 + tid];
        id = min(max(id, 0), ROWS_W - 1);
        sids[tid]  = id;
        sbias[tid] = bias[id];
    }
    __syncthreads();

    // ---- loader coords ----
    const int arow  = tid >> 1;        // 128 weight rows, 2 threads/row
    const int ahalf = tid & 1;         // 32-float half of the 64-float chunk row
    const uint32_t a_sts = sw128((uint32_t)arow * 128u + (uint32_t)ahalf * 64u);
    const int brow  = tid >> 1;        // 128 x rows
    const int bhalf = tid & 1;

    // ---- warp / mma coords ----
    const int warp_m = wid & 3;        // 4 warps along samples (M)
    const int warp_n = wid >> 2;       // 2 warps along x rows (N)
    // A frag ldmatrix lane address pieces (per mt, ks): row within tile + 16B sub
    const uint32_t a_lrow = (uint32_t)(warp_m * 32 + (lid & 15));
    const uint32_t a_lsub = (uint32_t)(lid >> 4) * 16u;
    // B frag lane pieces (per nf2, ks)
    const uint32_t b_lrow = (uint32_t)(warp_n * 64 + ((lid >> 4) & 1) * 8 + (lid & 7));
    const uint32_t b_lko  = (uint32_t)((lid >> 3) & 1) * 16u;

    float d[2][8][4];
    #pragma unroll
    for (int mt = 0; mt < 2; mt++)
        #pragma unroll
        for (int nf = 0; nf < 8; nf++)
            #pragma unroll
            for (int r = 0; r < 4; r++) d[mt][nf][r] = 0.f;

    float4 av[8];

    // ---------- prologue: chunk 0 ----------
    {
        const float* wrow = weight + (size_t)sids[arow] * D_K + ahalf * 32;
        #pragma unroll
        for (int j = 0; j < 8; j++) av[j] = reinterpret_cast<const float4*>(wrow)[j];
        const __nv_bfloat16* xh = g_xh + (size_t)(n0 + brow) * D_K + bhalf * 32;
        const __nv_bfloat16* xl = g_xl + (size_t)(n0 + brow) * D_K + bhalf * 32;
        #pragma unroll
        for (int j = 0; j < 4; j++) {
            uint32_t dsto = sw128((uint32_t)brow * 128u + (uint32_t)(bhalf * 4 + j) * 16u);
            cp16(sb + BH + dsto, xh + j * 8);
            cp16(sb + BL + dsto, xl + j * 8);
        }
        #pragma unroll
        for (int j = 0; j < 8; j++) {
            float4 v = av[j];
            __nv_bfloat16 h0 = __float2bfloat16_rn(v.x), h1 = __float2bfloat16_rn(v.y);
            __nv_bfloat16 h2 = __float2bfloat16_rn(v.z), h3 = __float2bfloat16_rn(v.w);
            uint2 hv, lv;
            hv.x = pk(h0, h1); hv.y = pk(h2, h3);
            lv.x = pkf(v.x - __bfloat162float(h0), v.y - __bfloat162float(h1));
            lv.y = pkf(v.z - __bfloat162float(h2), v.w - __bfloat162float(h3));
            uint32_t o = a_sts + (uint32_t)j * 8u;
            o = sw128((uint32_t)arow * 128u + (uint32_t)ahalf * 64u + (uint32_t)j * 8u);
            *reinterpret_cast<uint2*>(smc + AH + o) = hv;
            *reinterpret_cast<uint2*>(smc + AL + o) = lv;
        }
        asm volatile("cp.async.wait_all;" ::: "memory");
        __syncthreads();
    }

    // ---------- main loop ----------
    for (int c = 0; c < NCH; c++) {
        const uint32_t cur = (uint32_t)(c & 1) * STAGE;
        const uint32_t nxt = (uint32_t)((c + 1) & 1) * STAGE;

        if (c + 1 < NCH) {
            const float* wrow = weight + (size_t)sids[arow] * D_K + (c + 1) * KC + ahalf * 32;
            #pragma unroll
            for (int j = 0; j < 8; j++) av[j] = reinterpret_cast<const float4*>(wrow)[j];
            const __nv_bfloat16* xh = g_xh + (size_t)(n0 + brow) * D_K + (c + 1) * KC + bhalf * 32;
            const __nv_bfloat16* xl = g_xl + (size_t)(n0 + brow) * D_K + (c + 1) * KC + bhalf * 32;
            #pragma unroll
            for (int j = 0; j < 4; j++) {
                uint32_t dsto = sw128((uint32_t)brow * 128u + (uint32_t)(bhalf * 4 + j) * 16u);
                cp16(sb + nxt + BH + dsto, xh + j * 8);
                cp16(sb + nxt + BL + dsto, xl + j * 8);
            }
        }

        // ---- compute chunk c ----
        #pragma unroll
        for (int ks = 0; ks < 4; ks++) {
            uint32_t ah[2][4], al[2][4], bh[8][2], bl[8][2];
            #pragma unroll
            for (int mt = 0; mt < 2; mt++) {
                uint32_t off = sw128((a_lrow + (uint32_t)mt * 16u) * 128u +
                                     (uint32_t)ks * 32u + a_lsub);
                ldsm4(sb + cur + AH + off, ah[mt][0], ah[mt][1], ah[mt][2], ah[mt][3]);
                ldsm4(sb + cur + AL + off, al[mt][0], al[mt][1], al[mt][2], al[mt][3]);
            }
            #pragma unroll
            for (int nf2 = 0; nf2 < 4; nf2++) {
                uint32_t off = sw128((b_lrow + (uint32_t)nf2 * 16u) * 128u +
                                     (uint32_t)ks * 32u + b_lko);
                ldsm4(sb + cur + BH + off, bh[2*nf2][0], bh[2*nf2][1],
                      bh[2*nf2+1][0], bh[2*nf2+1][1]);
                ldsm4(sb + cur + BL + off, bl[2*nf2][0], bl[2*nf2][1],
                      bl[2*nf2+1][0], bl[2*nf2+1][1]);
            }
            #pragma unroll
            for (int mt = 0; mt < 2; mt++)
                #pragma unroll
                for (int nf = 0; nf < 8; nf++) {
                    mma16816(d[mt][nf], ah[mt], bh[nf]);
                    mma16816(d[mt][nf], ah[mt], bl[nf]);
                    mma16816(d[mt][nf], al[mt], bh[nf]);
                }
        }

        if (c + 1 < NCH) {
            #pragma unroll
            for (int j = 0; j < 8; j++) {
                float4 v = av[j];
                __nv_bfloat16 h0 = __float2bfloat16_rn(v.x), h1 = __float2bfloat16_rn(v.y);
                __nv_bfloat16 h2 = __float2bfloat16_rn(v.z), h3 = __float2bfloat16_rn(v.w);
                uint2 hv, lv;
                hv.x = pk(h0, h1); hv.y = pk(h2, h3);
                lv.x = pkf(v.x - __bfloat162float(h0), v.y - __bfloat162float(h1));
                lv.y = pkf(v.z - __bfloat162float(h2), v.w - __bfloat162float(h3));
                uint32_t o = sw128((uint32_t)arow * 128u + (uint32_t)ahalf * 64u + (uint32_t)j * 8u);
                *reinterpret_cast<uint2*>(smc + nxt + AH + o) = hv;
                *reinterpret_cast<uint2*>(smc + nxt + AL + o) = lv;
            }
        }
        asm volatile("cp.async.wait_all;" ::: "memory");
        __syncthreads();
    }

    // ---------- epilogue: transpose through smem, add bias, coalesced stores ----
    float* C = reinterpret_cast<float*>(smc);   // 128 x CSTRIDE floats (66.6KB)
    #pragma unroll
    for (int mt = 0; mt < 2; mt++) {
        int m0r = warp_m * 32 + mt * 16 + (lid >> 2);
        float b0v = sbias[m0r];
        float b1v = sbias[m0r + 8];
        #pragma unroll
        for (int nf = 0; nf < 8; nf++) {
            int nc = warp_n * 64 + nf * 8 + (lid & 3) * 2;
            float2 v0 = { d[mt][nf][0] + b0v, d[mt][nf][1] + b0v };
            float2 v1 = { d[mt][nf][2] + b1v, d[mt][nf][3] + b1v };
            *reinterpret_cast<float2*>(&C[(size_t)m0r * CSTRIDE + nc])       = v0;
            *reinterpret_cast<float2*>(&C[(size_t)(m0r + 8) * CSTRIDE + nc]) = v1;
        }
    }
    __syncthreads();

    {
        const int n_loc = tid >> 1;       // output row within tile
        const int sh    = tid & 1;        // which 64-sample half
        float* orow = out + (size_t)(n0 + n_loc) * S_ALL + s0 + sh * 64;
        #pragma unroll
        for (int i = 0; i < 16; i++) {
            int s = sh * 64 + i * 4;
            float4 v;
            v.x = C[(size_t)(s + 0) * CSTRIDE + n_loc];
            v.y = C[(size_t)(s + 1) * CSTRIDE + n_loc];
            v.z = C[(size_t)(s + 2) * CSTRIDE + n_loc];
            v.w = C[(size_t)(s + 3) * CSTRIDE + n_loc];
            reinterpret_cast<float4*>(orow)[i] = v;
        }
    }
}

extern "C" void kernel_launch(void* const* d_in, const int* in_sizes, int n_in,
                              void* d_out, int out_size)
{
    const float* x    = (const float*)d_in[0];
    const float* w    = (const float*)d_in[1];
    const float* bias = (const float*)d_in[2];
    const int*   ids  = (const int*)d_in[3];
    float*       out  = (float*)d_out;

    cudaFuncSetAttribute(lsh_mma_gemm, cudaFuncAttributeMaxDynamicSharedMemorySize,
                         SMEM_BYTES);

    split_x_kernel<<<128, 256>>>(x);
    dim3 grid(NX / NTILE, S_ALL / STILE);   // (2, 256): n-half fastest
    lsh_mma_gemm<<<grid, 256, SMEM_BYTES>>>(w, bias, ids, out);
}

// round 5
// speedup vs baseline: 2.3671x; 1.2570x over previous
#include <cuda_runtime.h>
#include <cuda_bf16.h>
#include <cstdint>

// out[n][s] = dot(x[n,:], weight[ids[s],:]) + bias[ids[s]]
//   x [256,512] f32, weight [500001,512] f32, bias [500001] f32, ids [32768] i32
//   out [256, 32768] f32
// bf16x3 split GEMM on mma.sync. Round 5: 512 threads / 16 warps per CTA,
// warp tile 32x32, to lift occupancy 12%->25% and feed the tensor pipe.

namespace {
constexpr int D_K    = 512;
constexpr int NX     = 256;
constexpr int S_ALL  = 32768;
constexpr int ROWS_W = 500001;
constexpr int STILE  = 128;        // samples per CTA (GEMM M)
constexpr int NTILE  = 128;        // x rows per CTA (GEMM N)
constexpr int KC     = 64;         // f32 K elems per chunk
constexpr int NCH    = D_K / KC;   // 8
constexpr int THREADS = 512;

// smem stage layout (bytes): Ah, Al, Bh, Bl each 128 rows x 64 bf16 (128B rows)
constexpr uint32_t AH = 0, AL = 16384, BH = 32768, BL = 49152;
constexpr uint32_t STAGE = 65536;
constexpr uint32_t SMEM_BYTES = 2 * STAGE;   // 128KB (epilogue reuses this)
constexpr int CSTRIDE = 130;       // f32 stride of epilogue staging
}

__device__ __nv_bfloat16 g_xh[NX * D_K];
__device__ __nv_bfloat16 g_xl[NX * D_K];

__device__ __forceinline__ uint32_t smem_u32(const void* p) {
    uint32_t a;
    asm("{ .reg .u64 t; cvta.to.shared.u64 t, %1; cvt.u32.u64 %0, t; }" : "=r"(a) : "l"(p));
    return a;
}
__device__ __forceinline__ uint32_t sw128(uint32_t o) { return o ^ ((o >> 3) & 0x70u); }

__device__ __forceinline__ uint32_t pk(__nv_bfloat16 a, __nv_bfloat16 b) {
    __nv_bfloat162 t = __halves2bfloat162(a, b);
    return *reinterpret_cast<uint32_t*>(&t);
}
__device__ __forceinline__ uint32_t pkf(float a, float b) {
    __nv_bfloat162 t = __floats2bfloat162_rn(a, b);
    return *reinterpret_cast<uint32_t*>(&t);
}

__device__ __forceinline__ void ldsm4(uint32_t addr, uint32_t& r0, uint32_t& r1,
                                      uint32_t& r2, uint32_t& r3) {
    asm volatile("ldmatrix.sync.aligned.m8n8.x4.shared.b16 {%0,%1,%2,%3}, [%4];"
                 : "=r"(r0), "=r"(r1), "=r"(r2), "=r"(r3) : "r"(addr));
}
__device__ __forceinline__ void mma16816(float* d, const uint32_t* a, const uint32_t* b) {
    asm volatile(
        "mma.sync.aligned.m16n8k16.row.col.f32.bf16.bf16.f32 "
        "{%0,%1,%2,%3}, {%4,%5,%6,%7}, {%8,%9}, {%0,%1,%2,%3};"
        : "+f"(d[0]), "+f"(d[1]), "+f"(d[2]), "+f"(d[3])
        : "r"(a[0]), "r"(a[1]), "r"(a[2]), "r"(a[3]), "r"(b[0]), "r"(b[1]));
}
__device__ __forceinline__ void cp16(uint32_t dst, const void* src) {
    asm volatile("cp.async.ca.shared.global [%0], [%1], 16;" :: "r"(dst), "l"(src));
}

// ---------- kernel 1: split x into bf16 hi/lo ----------
__global__ void split_x_kernel(const float* __restrict__ x) {
    int i = blockIdx.x * blockDim.x + threadIdx.x;   // over 32768 float4s
    float4 v = reinterpret_cast<const float4*>(x)[i];
    __nv_bfloat16 h0 = __float2bfloat16_rn(v.x), h1 = __float2bfloat16_rn(v.y);
    __nv_bfloat16 h2 = __float2bfloat16_rn(v.z), h3 = __float2bfloat16_rn(v.w);
    uint2 hv, lv;
    hv.x = pk(h0, h1);  hv.y = pk(h2, h3);
    lv.x = pkf(v.x - __bfloat162float(h0), v.y - __bfloat162float(h1));
    lv.y = pkf(v.z - __bfloat162float(h2), v.w - __bfloat162float(h3));
    reinterpret_cast<uint2*>(g_xh)[i] = hv;
    reinterpret_cast<uint2*>(g_xl)[i] = lv;
}

// ---------- kernel 2: GEMM ----------
__global__ void __launch_bounds__(THREADS, 1)
lsh_mma_gemm(const float* __restrict__ weight,
             const float* __restrict__ bias,
             const int* __restrict__ sample_ids,
             float* __restrict__ out)
{
    extern __shared__ float4 smem4[];
    char* smc = reinterpret_cast<char*>(smem4);
    const uint32_t sb = smem_u32(smc);

    __shared__ int   sids[STILE];
    __shared__ float sbias[STILE];

    const int tid = threadIdx.x;
    const int wid = tid >> 5;
    const int lid = tid & 31;
    const int n0  = blockIdx.x * NTILE;    // x-row half (0 or 128)
    const int s0  = blockIdx.y * STILE;    // sample tile

    if (tid < STILE) {
        int id = sample_ids[s0 + tid];
        id = min(max(id, 0), ROWS_W - 1);
        sids[tid]  = id;
        sbias[tid] = bias[id];
    }
    __syncthreads();

    // ---- loader coords ----
    const int arow = tid >> 2;               // 128 weight rows, 4 threads/row
    const int aq   = (tid & 3) * 16;         // 16-float segment within 64-float row

    // ---- warp / mma coords: 4x4 warp grid, warp tile 32x32 ----
    const int warp_m = wid & 3;
    const int warp_n = wid >> 2;
    const uint32_t a_lrow = (uint32_t)(warp_m * 32 + (lid & 15));
    const uint32_t a_lsub = (uint32_t)(lid >> 4) * 16u;
    const uint32_t b_lrow0 = (uint32_t)(warp_n * 32 + ((lid >> 4) & 1) * 8 + (lid & 7));
    const uint32_t b_lko   = (uint32_t)((lid >> 3) & 1) * 16u;

    float d[2][4][4];
    #pragma unroll
    for (int mt = 0; mt < 2; mt++)
        #pragma unroll
        for (int nf = 0; nf < 4; nf++)
            #pragma unroll
            for (int r = 0; r < 4; r++) d[mt][nf][r] = 0.f;

    float4 av[4];

    auto loadA = [&](int c) {
        const float* wrow = weight + (size_t)sids[arow] * D_K + c * KC + aq;
        #pragma unroll
        for (int j = 0; j < 4; j++) av[j] = reinterpret_cast<const float4*>(wrow)[j];
    };
    auto cpB = [&](int c, uint32_t stg) {
        #pragma unroll
        for (int p = 0; p < 2; p++) {
            int idx = tid + p * THREADS;     // 1024 segments
            int row = idx >> 3, sg = idx & 7;
            size_t gi = (size_t)(n0 + row) * D_K + c * KC + sg * 8;
            uint32_t dsto = sw128((uint32_t)row * 128u + (uint32_t)sg * 16u);
            cp16(sb + stg + BH + dsto, g_xh + gi);
            cp16(sb + stg + BL + dsto, g_xl + gi);
        }
    };
    auto storeA = [&](uint32_t stg) {
        #pragma unroll
        for (int j = 0; j < 4; j++) {
            float4 v = av[j];
            __nv_bfloat16 h0 = __float2bfloat16_rn(v.x), h1 = __float2bfloat16_rn(v.y);
            __nv_bfloat16 h2 = __float2bfloat16_rn(v.z), h3 = __float2bfloat16_rn(v.w);
            uint2 hv, lv;
            hv.x = pk(h0, h1); hv.y = pk(h2, h3);
            lv.x = pkf(v.x - __bfloat162float(h0), v.y - __bfloat162float(h1));
            lv.y = pkf(v.z - __bfloat162float(h2), v.w - __bfloat162float(h3));
            uint32_t o = sw128((uint32_t)arow * 128u + (uint32_t)(aq + j * 4) * 2u);
            *reinterpret_cast<uint2*>(smc + stg + AH + o) = hv;
            *reinterpret_cast<uint2*>(smc + stg + AL + o) = lv;
        }
    };

    // ---------- prologue: chunk 0 ----------
    loadA(0);
    cpB(0, 0);
    storeA(0);
    asm volatile("cp.async.wait_all;" ::: "memory");
    __syncthreads();

    // ---------- main loop ----------
    for (int c = 0; c < NCH; c++) {
        const uint32_t cur = (uint32_t)(c & 1) * STAGE;
        const uint32_t nxt = (uint32_t)((c + 1) & 1) * STAGE;

        if (c + 1 < NCH) {
            loadA(c + 1);
            cpB(c + 1, nxt);
        }

        // ---- compute chunk c ----
        #pragma unroll
        for (int ks = 0; ks < 4; ks++) {
            uint32_t ah[2][4], al[2][4], bh[4][2], bl[4][2];
            #pragma unroll
            for (int mt = 0; mt < 2; mt++) {
                uint32_t off = sw128((a_lrow + (uint32_t)mt * 16u) * 128u +
                                     (uint32_t)ks * 32u + a_lsub);
                ldsm4(sb + cur + AH + off, ah[mt][0], ah[mt][1], ah[mt][2], ah[mt][3]);
                ldsm4(sb + cur + AL + off, al[mt][0], al[mt][1], al[mt][2], al[mt][3]);
            }
            #pragma unroll
            for (int nf2 = 0; nf2 < 2; nf2++) {
                uint32_t off = sw128((b_lrow0 + (uint32_t)nf2 * 16u) * 128u +
                                     (uint32_t)ks * 32u + b_lko);
                ldsm4(sb + cur + BH + off, bh[2*nf2][0], bh[2*nf2][1],
                      bh[2*nf2+1][0], bh[2*nf2+1][1]);
                ldsm4(sb + cur + BL + off, bl[2*nf2][0], bl[2*nf2][1],
                      bl[2*nf2+1][0], bl[2*nf2+1][1]);
            }
            #pragma unroll
            for (int mt = 0; mt < 2; mt++)
                #pragma unroll
                for (int nf = 0; nf < 4; nf++) {
                    mma16816(d[mt][nf], ah[mt], bh[nf]);
                    mma16816(d[mt][nf], ah[mt], bl[nf]);
                    mma16816(d[mt][nf], al[mt], bh[nf]);
                }
        }

        if (c + 1 < NCH) storeA(nxt);
        asm volatile("cp.async.wait_all;" ::: "memory");
        __syncthreads();
    }

    // ---------- epilogue: smem transpose [m][n] stride 130, bias, coalesced out
    float* C = reinterpret_cast<float*>(smc);
    #pragma unroll
    for (int mt = 0; mt < 2; mt++) {
        int m0r = warp_m * 32 + mt * 16 + (lid >> 2);
        float b0v = sbias[m0r];
        float b1v = sbias[m0r + 8];
        #pragma unroll
        for (int nf = 0; nf < 4; nf++) {
            int nc = warp_n * 32 + nf * 8 + (lid & 3) * 2;
            float2 v0 = { d[mt][nf][0] + b0v, d[mt][nf][1] + b0v };
            float2 v1 = { d[mt][nf][2] + b1v, d[mt][nf][3] + b1v };
            *reinterpret_cast<float2*>(&C[(size_t)m0r * CSTRIDE + nc])       = v0;
            *reinterpret_cast<float2*>(&C[(size_t)(m0r + 8) * CSTRIDE + nc]) = v1;
        }
    }
    __syncthreads();

    {
        // thread (n_loc, q): outputs samples s = q*4 + i*16 (+0..3), i=0..7
        // smem read bank = (2m + n) mod 32 = 8q + 2k + n_loc (+32i) -> 32 distinct
        const int n_loc = tid >> 2;
        const int q     = tid & 3;
        float* orow = out + (size_t)(n0 + n_loc) * S_ALL + s0;
        #pragma unroll
        for (int i = 0; i < 8; i++) {
            int s = q * 4 + i * 16;
            float4 v;
            v.x = C[(size_t)(s + 0) * CSTRIDE + n_loc];
            v.y = C[(size_t)(s + 1) * CSTRIDE + n_loc];
            v.z = C[(size_t)(s + 2) * CSTRIDE + n_loc];
            v.w = C[(size_t)(s + 3) * CSTRIDE + n_loc];
            *reinterpret_cast<float4*>(orow + s) = v;
        }
    }
}

extern "C" void kernel_launch(void* const* d_in, const int* in_sizes, int n_in,
                              void* d_out, int out_size)
{
    const float* x    = (const float*)d_in[0];
    const float* w    = (const float*)d_in[1];
    const float* bias = (const float*)d_in[2];
    const int*   ids  = (const int*)d_in[3];
    float*       out  = (float*)d_out;

    cudaFuncSetAttribute(lsh_mma_gemm, cudaFuncAttributeMaxDynamicSharedMemorySize,
                         SMEM_BYTES);

    split_x_kernel<<<128, 256>>>(x);
    dim3 grid(NX / NTILE, S_ALL / STILE);   // (2, 256): n-half fastest
    lsh_mma_gemm<<<grid, THREADS, SMEM_BYTES>>>(w, bias, ids, out);
}

// round 6
// speedup vs baseline: 2.7281x; 1.1525x over previous
#include <cuda_runtime.h>
#include <cuda_bf16.h>
#include <cstdint>

// out[n][s] = dot(x[n,:], weight[ids[s],:]) + bias[ids[s]]
//   x [256,512] f32, weight [500001,512] f32, bias [500001] f32, ids [32768] i32
//   out [256, 32768] f32
// bf16x3 split GEMM on mma.sync. Round 6: 256-thread CTAs, tile 64x128,
// 2 CTAs/SM so barriers/loads of one CTA overlap compute of the other.

namespace {
constexpr int D_K    = 512;
constexpr int NX     = 256;
constexpr int S_ALL  = 32768;
constexpr int ROWS_W = 500001;
constexpr int STILE  = 64;         // samples per CTA (GEMM M)
constexpr int NTILE  = 128;        // x rows per CTA (GEMM N)
constexpr int KC     = 64;         // f32 K elems per chunk
constexpr int NCH    = D_K / KC;   // 8
constexpr int THREADS = 256;

// smem stage layout (bytes): Ah/Al 64 rows x 128B, Bh/Bl 128 rows x 128B
constexpr uint32_t AH = 0, AL = 8192, BH = 16384, BL = 32768;
constexpr uint32_t STAGE = 49152;            // 48KB
constexpr uint32_t SMEM_BYTES = 2 * STAGE;   // 96KB (epilogue reuses this)
constexpr int CSTRIDE = 132;       // f32 stride of epilogue staging (64 x 132)
}

__device__ __nv_bfloat16 g_xh[NX * D_K];
__device__ __nv_bfloat16 g_xl[NX * D_K];

__device__ __forceinline__ uint32_t smem_u32(const void* p) {
    uint32_t a;
    asm("{ .reg .u64 t; cvta.to.shared.u64 t, %1; cvt.u32.u64 %0, t; }" : "=r"(a) : "l"(p));
    return a;
}
__device__ __forceinline__ uint32_t sw128(uint32_t o) { return o ^ ((o >> 3) & 0x70u); }

__device__ __forceinline__ uint32_t pk(__nv_bfloat16 a, __nv_bfloat16 b) {
    __nv_bfloat162 t = __halves2bfloat162(a, b);
    return *reinterpret_cast<uint32_t*>(&t);
}
__device__ __forceinline__ uint32_t pkf(float a, float b) {
    __nv_bfloat162 t = __floats2bfloat162_rn(a, b);
    return *reinterpret_cast<uint32_t*>(&t);
}

__device__ __forceinline__ void ldsm4(uint32_t addr, uint32_t& r0, uint32_t& r1,
                                      uint32_t& r2, uint32_t& r3) {
    asm volatile("ldmatrix.sync.aligned.m8n8.x4.shared.b16 {%0,%1,%2,%3}, [%4];"
                 : "=r"(r0), "=r"(r1), "=r"(r2), "=r"(r3) : "r"(addr));
}
__device__ __forceinline__ void mma16816(float* d, const uint32_t* a, const uint32_t* b) {
    asm volatile(
        "mma.sync.aligned.m16n8k16.row.col.f32.bf16.bf16.f32 "
        "{%0,%1,%2,%3}, {%4,%5,%6,%7}, {%8,%9}, {%0,%1,%2,%3};"
        : "+f"(d[0]), "+f"(d[1]), "+f"(d[2]), "+f"(d[3])
        : "r"(a[0]), "r"(a[1]), "r"(a[2]), "r"(a[3]), "r"(b[0]), "r"(b[1]));
}
__device__ __forceinline__ void cp16(uint32_t dst, const void* src) {
    asm volatile("cp.async.ca.shared.global [%0], [%1], 16;" :: "r"(dst), "l"(src));
}

// ---------- kernel 1: split x into bf16 hi/lo ----------
__global__ void split_x_kernel(const float* __restrict__ x) {
    int i = blockIdx.x * blockDim.x + threadIdx.x;   // over 32768 float4s
    float4 v = reinterpret_cast<const float4*>(x)[i];
    __nv_bfloat16 h0 = __float2bfloat16_rn(v.x), h1 = __float2bfloat16_rn(v.y);
    __nv_bfloat16 h2 = __float2bfloat16_rn(v.z), h3 = __float2bfloat16_rn(v.w);
    uint2 hv, lv;
    hv.x = pk(h0, h1);  hv.y = pk(h2, h3);
    lv.x = pkf(v.x - __bfloat162float(h0), v.y - __bfloat162float(h1));
    lv.y = pkf(v.z - __bfloat162float(h2), v.w - __bfloat162float(h3));
    reinterpret_cast<uint2*>(g_xh)[i] = hv;
    reinterpret_cast<uint2*>(g_xl)[i] = lv;
}

// ---------- kernel 2: GEMM ----------
__global__ void __launch_bounds__(THREADS, 2)
lsh_mma_gemm(const float* __restrict__ weight,
             const float* __restrict__ bias,
             const int* __restrict__ sample_ids,
             float* __restrict__ out)
{
    extern __shared__ float4 smem4[];
    char* smc = reinterpret_cast<char*>(smem4);
    const uint32_t sb = smem_u32(smc);

    __shared__ int   sids[STILE];
    __shared__ float sbias[STILE];

    const int tid = threadIdx.x;
    const int wid = tid >> 5;
    const int lid = tid & 31;
    const int n0  = blockIdx.x * NTILE;    // x-row half (0 or 128)
    const int s0  = blockIdx.y * STILE;    // sample tile

    if (tid < STILE) {
        int id = sample_ids[s0 + tid];
        id = min(max(id, 0), ROWS_W - 1);
        sids[tid]  = id;
        sbias[tid] = bias[id];
    }
    __syncthreads();

    // ---- loader coords: A = 64 gathered weight rows, 4 threads/row ----
    const int arow = tid >> 2;               // 0..63
    const int aq   = (tid & 3) * 16;         // 16-float segment within 64-float row

    // ---- warp / mma coords: 2x4 warp grid (M x N), warp tile 32x32 ----
    const int warp_m = wid & 1;
    const int warp_n = wid >> 1;
    const uint32_t a_lrow  = (uint32_t)(warp_m * 32 + (lid & 15));
    const uint32_t a_lsub  = (uint32_t)(lid >> 4) * 16u;
    const uint32_t b_lrow0 = (uint32_t)(warp_n * 32 + ((lid >> 4) & 1) * 8 + (lid & 7));
    const uint32_t b_lko   = (uint32_t)((lid >> 3) & 1) * 16u;

    float d[2][4][4];
    #pragma unroll
    for (int mt = 0; mt < 2; mt++)
        #pragma unroll
        for (int nf = 0; nf < 4; nf++)
            #pragma unroll
            for (int r = 0; r < 4; r++) d[mt][nf][r] = 0.f;

    float4 av[4];

    auto loadA = [&](int c) {
        const float* wrow = weight + (size_t)sids[arow] * D_K + c * KC + aq;
        #pragma unroll
        for (int j = 0; j < 4; j++) av[j] = reinterpret_cast<const float4*>(wrow)[j];
    };
    auto cpB = [&](int c, uint32_t stg) {
        #pragma unroll
        for (int p = 0; p < 4; p++) {
            int idx = tid + p * THREADS;     // 1024 segments: 128 rows x 8 segs
            int row = idx >> 3, sg = idx & 7;
            size_t gi = (size_t)(n0 + row) * D_K + c * KC + sg * 8;
            uint32_t dsto = sw128((uint32_t)row * 128u + (uint32_t)sg * 16u);
            cp16(sb + stg + BH + dsto, g_xh + gi);
            cp16(sb + stg + BL + dsto, g_xl + gi);
        }
    };
    auto storeA = [&](uint32_t stg) {
        #pragma unroll
        for (int j = 0; j < 4; j++) {
            float4 v = av[j];
            __nv_bfloat16 h0 = __float2bfloat16_rn(v.x), h1 = __float2bfloat16_rn(v.y);
            __nv_bfloat16 h2 = __float2bfloat16_rn(v.z), h3 = __float2bfloat16_rn(v.w);
            uint2 hv, lv;
            hv.x = pk(h0, h1); hv.y = pk(h2, h3);
            lv.x = pkf(v.x - __bfloat162float(h0), v.y - __bfloat162float(h1));
            lv.y = pkf(v.z - __bfloat162float(h2), v.w - __bfloat162float(h3));
            uint32_t o = sw128((uint32_t)arow * 128u + (uint32_t)(aq + j * 4) * 2u);
            *reinterpret_cast<uint2*>(smc + stg + AH + o) = hv;
            *reinterpret_cast<uint2*>(smc + stg + AL + o) = lv;
        }
    };

    // ---------- prologue: chunk 0 ----------
    loadA(0);
    cpB(0, 0);
    storeA(0);
    asm volatile("cp.async.wait_all;" ::: "memory");
    __syncthreads();

    // ---------- main loop ----------
    for (int c = 0; c < NCH; c++) {
        const uint32_t cur = (uint32_t)(c & 1) * STAGE;
        const uint32_t nxt = (uint32_t)((c + 1) & 1) * STAGE;

        if (c + 1 < NCH) {
            loadA(c + 1);
            cpB(c + 1, nxt);
        }

        // ---- compute chunk c ----
        #pragma unroll
        for (int ks = 0; ks < 4; ks++) {
            uint32_t ah[2][4], al[2][4], bh[4][2], bl[4][2];
            #pragma unroll
            for (int mt = 0; mt < 2; mt++) {
                uint32_t off = sw128((a_lrow + (uint32_t)mt * 16u) * 128u +
                                     (uint32_t)ks * 32u + a_lsub);
                ldsm4(sb + cur + AH + off, ah[mt][0], ah[mt][1], ah[mt][2], ah[mt][3]);
                ldsm4(sb + cur + AL + off, al[mt][0], al[mt][1], al[mt][2], al[mt][3]);
            }
            #pragma unroll
            for (int nf2 = 0; nf2 < 2; nf2++) {
                uint32_t off = sw128((b_lrow0 + (uint32_t)nf2 * 16u) * 128u +
                                     (uint32_t)ks * 32u + b_lko);
                ldsm4(sb + cur + BH + off, bh[2*nf2][0], bh[2*nf2][1],
                      bh[2*nf2+1][0], bh[2*nf2+1][1]);
                ldsm4(sb + cur + BL + off, bl[2*nf2][0], bl[2*nf2][1],
                      bl[2*nf2+1][0], bl[2*nf2+1][1]);
            }
            #pragma unroll
            for (int mt = 0; mt < 2; mt++)
                #pragma unroll
                for (int nf = 0; nf < 4; nf++) {
                    mma16816(d[mt][nf], ah[mt], bh[nf]);
                    mma16816(d[mt][nf], ah[mt], bl[nf]);
                    mma16816(d[mt][nf], al[mt], bh[nf]);
                }
        }

        if (c + 1 < NCH) storeA(nxt);
        asm volatile("cp.async.wait_all;" ::: "memory");
        __syncthreads();
    }

    // ---------- epilogue: smem transpose [m][n] stride 132, bias, coalesced out
    float* C = reinterpret_cast<float*>(smc);   // 64 x 132 f32 = 33.8KB
    #pragma unroll
    for (int mt = 0; mt < 2; mt++) {
        int m0r = warp_m * 32 + mt * 16 + (lid >> 2);
        float b0v = sbias[m0r];
        float b1v = sbias[m0r + 8];
        #pragma unroll
        for (int nf = 0; nf < 4; nf++) {
            int nc = warp_n * 32 + nf * 8 + (lid & 3) * 2;
            float2 v0 = { d[mt][nf][0] + b0v, d[mt][nf][1] + b0v };
            float2 v1 = { d[mt][nf][2] + b1v, d[mt][nf][3] + b1v };
            *reinterpret_cast<float2*>(&C[(size_t)m0r * CSTRIDE + nc])       = v0;
            *reinterpret_cast<float2*>(&C[(size_t)(m0r + 8) * CSTRIDE + nc]) = v1;
        }
    }
    __syncthreads();

    {
        // thread (n_loc, q): n_loc = output row within tile (0..127), q = 0/1
        // reads C[s][n_loc], s = q*4 + k*8 (+0..3): bank = 16q + n_loc -> no conflicts
        const int n_loc = tid >> 1;
        const int q     = tid & 1;
        float* orow = out + (size_t)(n0 + n_loc) * S_ALL + s0;
        #pragma unroll
        for (int k = 0; k < 8; k++) {
            int s = q * 4 + k * 8;
            float4 v;
            v.x = C[(size_t)(s + 0) * CSTRIDE + n_loc];
            v.y = C[(size_t)(s + 1) * CSTRIDE + n_loc];
            v.z = C[(size_t)(s + 2) * CSTRIDE + n_loc];
            v.w = C[(size_t)(s + 3) * CSTRIDE + n_loc];
            *reinterpret_cast<float4*>(orow + s) = v;
        }
    }
}

extern "C" void kernel_launch(void* const* d_in, const int* in_sizes, int n_in,
                              void* d_out, int out_size)
{
    const float* x    = (const float*)d_in[0];
    const float* w    = (const float*)d_in[1];
    const float* bias = (const float*)d_in[2];
    const int*   ids  = (const int*)d_in[3];
    float*       out  = (float*)d_out;

    cudaFuncSetAttribute(lsh_mma_gemm, cudaFuncAttributeMaxDynamicSharedMemorySize,
                         SMEM_BYTES);

    split_x_kernel<<<128, 256>>>(x);
    dim3 grid(NX / NTILE, S_ALL / STILE);   // (2, 512): n-half fastest -> L2 reuse
    lsh_mma_gemm<<<grid, THREADS, SMEM_BYTES>>>(w, bias, ids, out);
}